// round 10
// baseline (speedup 1.0000x reference)
#include <cuda_runtime.h>
#include <cuda_fp16.h>
#include <cstdint>

// DynamicHybridRouter via mma.sync fp16 3-product split GEMM.
// logits = x[M,2048] @ W^T[2048,64] + b; all-mature -> top-2 softmax scatter,
// any-immature -> softmax(logits/2).
//
// Precision: a = hi + lo/2048, hi = f16_rn(a), lo = f16_rn((a-hi)*2048).
// acc1 += ahi*bhi ; acc2 += ahi*blo + alo*bhi ; logits = acc1 + acc2/2048.
// Dropped lo*lo ~2^-24 rel -> logit err ~2e-7.
//
// R9: B fragments software-pipelined (half-tile double buffer, loads issued
// ~12 mma ahead of use); A register prefetch distance 1, issued at iteration
// top. 512 thr / 16 warps per CTA (8 M-slices x 2 k-groups).

constexpr int KD = 2048;
constexpr int NEXP = 64;
constexpr int BM = 128;
constexpr int NT = KD / 32;          // 64 k-tiles; 1 k16 step per warp each
constexpr int LGS = 68;
constexpr float TEMP_INV = 0.5f;
constexpr float LO_SCALE = 2048.0f;
constexpr float LO_INV = 1.0f / 2048.0f;

// [k16=128][e=64][fc=4] -> uint4 {hi(k=2fc,2fc+1), hi(2fc+8,2fc+9),
//                                 lo(2fc,2fc+1),   lo(2fc+8,2fc+9)}
__device__ uint4 g_wpack[128 * 64 * 4];

__device__ __forceinline__ uint32_t h2u(__half2 h) {
    return *reinterpret_cast<uint32_t*>(&h);
}

__global__ void __launch_bounds__(256) pack_w_kernel(const float* __restrict__ gw) {
    int i = blockIdx.x * 256 + threadIdx.x;     // 32768 items
    int fc = i & 3, e = (i >> 2) & 63, k16 = i >> 8;
    const float* p = gw + e * KD + k16 * 16 + 2 * fc;
    float2 v0 = make_float2(p[0], p[1]);
    float2 v8 = make_float2(p[8], p[9]);
    __half2 h0 = __float22half2_rn(v0);
    __half2 h8 = __float22half2_rn(v8);
    float2 f0 = __half22float2(h0);
    float2 f8 = __half22float2(h8);
    __half2 l0 = __float22half2_rn(
        make_float2((v0.x - f0.x) * LO_SCALE, (v0.y - f0.y) * LO_SCALE));
    __half2 l8 = __float22half2_rn(
        make_float2((v8.x - f8.x) * LO_SCALE, (v8.y - f8.y) * LO_SCALE));
    uint4 q;
    q.x = h2u(h0); q.y = h2u(h8); q.z = h2u(l0); q.w = h2u(l8);
    g_wpack[i] = q;
}

__device__ __forceinline__ void mma16(float* d, const uint32_t* a,
                                      uint32_t b0, uint32_t b1) {
    asm volatile(
        "mma.sync.aligned.m16n8k16.row.col.f32.f16.f16.f32 "
        "{%0,%1,%2,%3}, {%4,%5,%6,%7}, {%8,%9}, {%0,%1,%2,%3};"
        : "+f"(d[0]), "+f"(d[1]), "+f"(d[2]), "+f"(d[3])
        : "r"(a[0]), "r"(a[1]), "r"(a[2]), "r"(a[3]), "r"(b0), "r"(b1));
}

__device__ __forceinline__ void cvt_hilo(float2 v, uint32_t& hi, uint32_t& lo) {
    __half2 h = __float22half2_rn(v);
    float2 f = __half22float2(h);
    __half2 l2 = __float22half2_rn(
        make_float2((v.x - f.x) * LO_SCALE, (v.y - f.y) * LO_SCALE));
    hi = h2u(h);
    lo = h2u(l2);
}

__global__ void __launch_bounds__(512, 1)
router_fp16(const float* __restrict__ x,
            const float* __restrict__ gb,
            const int*   __restrict__ mat,
            float*       __restrict__ out)
{
    __shared__ __align__(16) float lg[BM * LGS + NEXP];
    float* sbias = lg + BM * LGS;

    const int tid = threadIdx.x;
    const int w   = tid >> 5;
    const int l   = tid & 31;
    const int fr  = l >> 2;           // A row-in-group / B n-in-group
    const int fc  = l & 3;            // fragment k quad
    const int ms  = w & 7;            // M slice (16 rows)
    const int kg  = w >> 3;           // k16 half of each 32-k tile
    const int blockRow = blockIdx.x * BM;

    int imm = 0;
    if (tid < NEXP) {
        imm = (mat[tid] == 0) ? 1 : 0;
        sbias[tid] = gb[tid];
    }
    const int anyImm = __syncthreads_or(imm);

    float acc1[8][4], acc2[8][4];
#pragma unroll
    for (int nt = 0; nt < 8; ++nt)
#pragma unroll
        for (int q = 0; q < 4; ++q) { acc1[nt][q] = 0.f; acc2[nt][q] = 0.f; }

    // per-lane A base: row (blockRow + ms*16 + fr), k offset kg*16 + 2*fc
    const float* xb = x + (size_t)(blockRow + ms * 16 + fr) * KD + kg * 16 + 2 * fc;

    // A stages: [rh*2 + kp] ; rh = row half (+8 rows), kp = k half (+8 k)
    float2 raw0[4], raw1[4];
#pragma unroll
    for (int rh = 0; rh < 2; ++rh)
#pragma unroll
        for (int kp = 0; kp < 2; ++kp)
            raw0[rh * 2 + kp] = *(const float2*)(xb + (size_t)(rh * 8) * KD + kp * 8);

    const uint4* wbase = g_wpack + (size_t)kg * 256 + fr * 4 + fc;

    // B double buffer: bq0 = current tile half0 / next tile half0,
    //                  bq1 = current tile half1
    uint4 bq0[4], bq1[4];
#pragma unroll
    for (int nt = 0; nt < 4; ++nt) bq0[nt] = wbase[nt * 32];   // tile0 half0

#pragma unroll 2
    for (int kt = 0; kt < NT; ++kt) {
        // ---- A prefetch for kt+1, issued first (full iteration to land) ----
        if (kt + 1 < NT) {
            const float* xt = xb + (kt + 1) * 32;
#pragma unroll
            for (int rh = 0; rh < 2; ++rh)
#pragma unroll
                for (int kp = 0; kp < 2; ++kp)
                    raw1[rh * 2 + kp] =
                        *(const float2*)(xt + (size_t)(rh * 8) * KD + kp * 8);
        }

        const uint4* wt = wbase + (size_t)(kt * 2) * 256;

        // ---- B prefetch: this tile's half1 (used after 12 mma) ----
#pragma unroll
        for (int nt = 0; nt < 4; ++nt) bq1[nt] = wt[(nt + 4) * 32];

        // ---- A hi/lo fragments (transient) ----
        uint32_t ahi[4], alo[4];
#pragma unroll
        for (int rh = 0; rh < 2; ++rh)
#pragma unroll
            for (int kp = 0; kp < 2; ++kp)
                cvt_hilo(raw0[rh * 2 + kp], ahi[kp * 2 + rh], alo[kp * 2 + rh]);

        // ---- half0: experts 0..31 with prefetched bq0 ----
#pragma unroll
        for (int nt = 0; nt < 4; ++nt) mma16(acc1[nt], ahi, bq0[nt].x, bq0[nt].y);
#pragma unroll
        for (int nt = 0; nt < 4; ++nt) mma16(acc2[nt], ahi, bq0[nt].z, bq0[nt].w);
#pragma unroll
        for (int nt = 0; nt < 4; ++nt) mma16(acc2[nt], alo, bq0[nt].x, bq0[nt].y);

        // ---- B prefetch: next tile's half0 (used next iteration) ----
        if (kt + 1 < NT) {
            const uint4* wn = wbase + (size_t)((kt + 1) * 2) * 256;
#pragma unroll
            for (int nt = 0; nt < 4; ++nt) bq0[nt] = wn[nt * 32];
        }

        // ---- half1: experts 32..63 with bq1 ----
#pragma unroll
        for (int nt = 0; nt < 4; ++nt) mma16(acc1[nt + 4], ahi, bq1[nt].x, bq1[nt].y);
#pragma unroll
        for (int nt = 0; nt < 4; ++nt) mma16(acc2[nt + 4], ahi, bq1[nt].z, bq1[nt].w);
#pragma unroll
        for (int nt = 0; nt < 4; ++nt) mma16(acc2[nt + 4], alo, bq1[nt].x, bq1[nt].y);

        // rotate A stage
#pragma unroll
        for (int j = 0; j < 4; ++j) raw0[j] = raw1[j];
    }

    // ---- k-split reduction into logits SMEM ----
    if (kg == 1) {
#pragma unroll
        for (int nt = 0; nt < 8; ++nt) {
            int row = ms * 16 + fr;
            int e = nt * 8 + fc * 2;
            *(float2*)&lg[row * LGS + e] = make_float2(
                fmaf(acc2[nt][0], LO_INV, acc1[nt][0]),
                fmaf(acc2[nt][1], LO_INV, acc1[nt][1]));
            *(float2*)&lg[(row + 8) * LGS + e] = make_float2(
                fmaf(acc2[nt][2], LO_INV, acc1[nt][2]),
                fmaf(acc2[nt][3], LO_INV, acc1[nt][3]));
        }
    }
    __syncthreads();
    if (kg == 0) {
#pragma unroll
        for (int nt = 0; nt < 8; ++nt) {
            int row = ms * 16 + fr;
            int e = nt * 8 + fc * 2;
            float2 bv = *(const float2*)&sbias[e];
            float2 o0 = *(float2*)&lg[row * LGS + e];
            o0.x += fmaf(acc2[nt][0], LO_INV, acc1[nt][0]) + bv.x;
            o0.y += fmaf(acc2[nt][1], LO_INV, acc1[nt][1]) + bv.y;
            *(float2*)&lg[row * LGS + e] = o0;
            float2 o1 = *(float2*)&lg[(row + 8) * LGS + e];
            o1.x += fmaf(acc2[nt][2], LO_INV, acc1[nt][2]) + bv.x;
            o1.y += fmaf(acc2[nt][3], LO_INV, acc1[nt][3]) + bv.y;
            *(float2*)&lg[(row + 8) * LGS + e] = o1;
        }
    }
    __syncthreads();

    // ---- routing epilogue (identical to the passing kernels) ----
    if (tid < BM) {
        float* lrow = &lg[tid * LGS];
        float* orow = out + (size_t)(blockRow + tid) * NEXP;

        if (!anyImm) {
            float v1 = -3.4e38f, v2 = -3.4e38f;
            int i1 = 0, i2 = 0;
#pragma unroll
            for (int e = 0; e < NEXP; ++e) {
                float v = lrow[e];
                if (v > v1) { v2 = v1; i2 = i1; v1 = v; i1 = e; }
                else if (v > v2) { v2 = v; i2 = e; }
            }
            float t = __expf(v2 - v1);
            float inv = 1.0f / (1.0f + t);
            float4 z = make_float4(0.f, 0.f, 0.f, 0.f);
#pragma unroll
            for (int j = 0; j < NEXP / 4; ++j) ((float4*)orow)[j] = z;
            orow[i1] = inv;
            orow[i2] = t * inv;
        } else {
            float mx = -3.4e38f;
#pragma unroll
            for (int e = 0; e < NEXP; ++e) mx = fmaxf(mx, lrow[e]);
            float sum = 0.f;
#pragma unroll
            for (int e = 0; e < NEXP; ++e) {
                float t = __expf((lrow[e] - mx) * TEMP_INV);
                lrow[e] = t;
                sum += t;
            }
            float inv = 1.0f / sum;
#pragma unroll
            for (int e = 0; e < NEXP; ++e) orow[e] = lrow[e] * inv;
        }
    }
}

extern "C" void kernel_launch(void* const* d_in, const int* in_sizes, int n_in,
                              void* d_out, int out_size) {
    const float* x  = (const float*)d_in[0];
    const float* gw = (const float*)d_in[1];
    const float* gb = (const float*)d_in[2];
    const int*   mt = (const int*)d_in[3];
    float* out = (float*)d_out;

    const int M = in_sizes[0] / KD;     // 16384
    pack_w_kernel<<<128, 256>>>(gw);
    router_fp16<<<M / BM, 512>>>(x, gb, mt, out);
}